// round 12
// baseline (speedup 1.0000x reference)
#include <cuda_runtime.h>
#include <cuda_fp16.h>
#include <math.h>

#define NN 100000
#define NE 1200000
#define D 64
#define NG 512
#define NL 3
#define BN_EPS 1e-5

#define SCAN_BLK 1024
#define NSCAN ((NN + SCAN_BLK - 1) / SCAN_BLK)   // 98

// Scratch (static device arrays; allocation is forbidden)
__device__ float g_agg[(size_t)NN * D];   // holds agg + x (fused)
__device__ float g_h[(size_t)NN * D];
__device__ float g_x[(size_t)NN * D];     // fp32 y (self-term source)
__device__ __half2 g_xh[(size_t)NN * 32]; // fp16 y (message-gather source)
__device__ double g_stats[2 * D];
__device__ float g_mu[D];
__device__ float g_rs[D];
__device__ int g_deg[NN];
__device__ int g_rowptr[NN];
__device__ int g_cursor[NN];
__device__ int g_bsum[NSCAN];
__device__ int2 g_edge[NE];               // {src, __float_as_int(w)}

// ---------------------------------------------------------------------------
// init: zero deg, stats, pooled-output region; convert input x -> fp16 rows
// ---------------------------------------------------------------------------
__global__ void init_kernel(const float* __restrict__ x,
                            float* __restrict__ out_pool) {
    int gid = blockIdx.x * blockDim.x + threadIdx.x;
    int stride = gridDim.x * blockDim.x;
    for (int i = gid; i < NN; i += stride) g_deg[i] = 0;
    if (out_pool)
        for (int i = gid; i < NG * (NL * D); i += stride) out_pool[i] = 0.f;
    if (gid < 2 * D) g_stats[gid] = 0.0;
    const float2* x2 = (const float2*)x;
    for (int i = gid; i < NN * 32; i += stride)
        g_xh[i] = __float22half2_rn(x2[i]);
}

// ---------------------------------------------------------------------------
// CSR build: histogram, scan, fill
// ---------------------------------------------------------------------------
__global__ void deg_kernel(const int* __restrict__ ei) {
    int e = blockIdx.x * blockDim.x + threadIdx.x;
    if (e < NE) {
        int dst = ei[NE + e];
        if ((unsigned)dst < NN) atomicAdd(&g_deg[dst], 1);
    }
}

__global__ void __launch_bounds__(SCAN_BLK) scanA_kernel() {
    __shared__ int sh[SCAN_BLK];
    int t = threadIdx.x;
    int i = blockIdx.x * SCAN_BLK + t;
    int v = (i < NN) ? g_deg[i] : 0;
    sh[t] = v;
    __syncthreads();
    for (int off = 1; off < SCAN_BLK; off <<= 1) {
        int add = (t >= off) ? sh[t - off] : 0;
        __syncthreads();
        sh[t] += add;
        __syncthreads();
    }
    if (i < NN) g_rowptr[i] = sh[t] - v;          // exclusive within block
    if (t == SCAN_BLK - 1) g_bsum[blockIdx.x] = sh[t];
}

__global__ void scanB_kernel() {                  // parallel scan of 98 blocks
    __shared__ int sh[128];
    int t = threadIdx.x;
    int v = (t < NSCAN) ? g_bsum[t] : 0;
    sh[t] = v;
    __syncthreads();
    for (int off = 1; off < 128; off <<= 1) {
        int add = (t >= off) ? sh[t - off] : 0;
        __syncthreads();
        sh[t] += add;
        __syncthreads();
    }
    if (t < NSCAN) g_bsum[t] = sh[t] - v;         // exclusive
}

__global__ void scanC_kernel() {
    int i = blockIdx.x * blockDim.x + threadIdx.x;
    if (i < NN) {
        int r = g_rowptr[i] + g_bsum[i / SCAN_BLK];
        g_rowptr[i] = r;
        g_cursor[i] = r;
    }
}

__global__ void fill_kernel(const int* __restrict__ ei,
                            const float* __restrict__ ew) {
    int e = blockIdx.x * blockDim.x + threadIdx.x;
    if (e < NE) {
        int src = ei[e];
        int dst = ei[NE + e];
        if ((unsigned)dst >= NN) return;
        int pos = atomicAdd(&g_cursor[dst], 1);
        g_edge[pos] = make_int2(src, __float_as_int(ew[e]));
    }
}

// ---------------------------------------------------------------------------
// gather-aggregate: warp per node.
//   messages gathered in fp16 (one 128B row load per edge), fp32 accumulate;
//   self term x[n] read fp32 from xbase.
// Lane owns features 2*lane, 2*lane+1.
// ---------------------------------------------------------------------------
__global__ void __launch_bounds__(256) agg_kernel(const float* __restrict__ x_in,
                                                  int use_gx) {
    const float* __restrict__ xbase = use_gx ? g_x : x_in;
    int wid = (blockIdx.x * blockDim.x + threadIdx.x) >> 5;
    int lane = threadIdx.x & 31;
    if (wid >= NN) return;
    int start = g_rowptr[wid];
    int deg = g_deg[wid];
    float a0 = 0.f, a1 = 0.f;
    int e = 0;
    for (; e + 2 <= deg; e += 2) {
        int2 e0 = g_edge[start + e];
        int2 e1 = g_edge[start + e + 1];
        float w0 = __int_as_float(e0.y);
        float w1 = __int_as_float(e1.y);
        float2 f0 = __half22float2(g_xh[(size_t)e0.x * 32 + lane]);
        float2 f1 = __half22float2(g_xh[(size_t)e1.x * 32 + lane]);
        a0 += w0 * f0.x;
        a1 += w0 * f0.y;
        a0 += w1 * f1.x;
        a1 += w1 * f1.y;
    }
    if (e < deg) {
        int2 e0 = g_edge[start + e];
        float w0 = __int_as_float(e0.y);
        float2 f0 = __half22float2(g_xh[(size_t)e0.x * 32 + lane]);
        a0 += w0 * f0.x;
        a1 += w0 * f0.y;
    }
    float2 s = *(const float2*)&xbase[(size_t)wid * D + 2 * lane];
    ((float2*)g_agg)[(size_t)wid * 32 + lane] = make_float2(a0 + s.x, a1 + s.y);
}

// ---------------------------------------------------------------------------
// fused MLP: h = relu(relu(A@W1^T + b1)@W2^T + b2), + BN partial sums
// A = g_agg (already includes +x). 64-row tile, 256 threads, 4x4 blocking.
// ---------------------------------------------------------------------------
__global__ void __launch_bounds__(256) mlp_kernel(
    const float* __restrict__ W1, const float* __restrict__ b1,
    const float* __restrict__ W2, const float* __restrict__ b2) {
    __shared__ __align__(16) float shA[64 * 68];
    __shared__ __align__(16) float shW[64 * 68];
    __shared__ float red[2 * D];

    int tid = threadIdx.x;
    int base = blockIdx.x * 64;
    if (tid < 2 * D) red[tid] = 0.f;

#pragma unroll
    for (int j = 0; j < 16; j++) {
        int idx = tid + j * 256;
        int r = idx >> 6, k = idx & 63;
        int n = base + r;
        shA[r * 68 + k] = (n < NN) ? g_agg[(size_t)n * D + k] : 0.f;
    }
#pragma unroll
    for (int j = 0; j < 16; j++) {
        int idx = tid + j * 256;
        shW[(idx & 63) * 68 + (idx >> 6)] = W1[idx];
    }
    __syncthreads();

    int tr = tid >> 4, tc = tid & 15;
    float acc[4][4];
#pragma unroll
    for (int i = 0; i < 4; i++)
#pragma unroll
        for (int j = 0; j < 4; j++) acc[i][j] = 0.f;

    for (int k = 0; k < 64; k++) {
        float4 wv = *(const float4*)&shW[k * 68 + tc * 4];
        float a0 = shA[(tr * 4 + 0) * 68 + k];
        float a1 = shA[(tr * 4 + 1) * 68 + k];
        float a2 = shA[(tr * 4 + 2) * 68 + k];
        float a3 = shA[(tr * 4 + 3) * 68 + k];
        acc[0][0] += a0 * wv.x; acc[0][1] += a0 * wv.y; acc[0][2] += a0 * wv.z; acc[0][3] += a0 * wv.w;
        acc[1][0] += a1 * wv.x; acc[1][1] += a1 * wv.y; acc[1][2] += a1 * wv.z; acc[1][3] += a1 * wv.w;
        acc[2][0] += a2 * wv.x; acc[2][1] += a2 * wv.y; acc[2][2] += a2 * wv.z; acc[2][3] += a2 * wv.w;
        acc[3][0] += a3 * wv.x; acc[3][1] += a3 * wv.y; acc[3][2] += a3 * wv.z; acc[3][3] += a3 * wv.w;
    }
    __syncthreads();

    float bb[4];
#pragma unroll
    for (int j = 0; j < 4; j++) bb[j] = b1[tc * 4 + j];
#pragma unroll
    for (int i = 0; i < 4; i++)
#pragma unroll
        for (int j = 0; j < 4; j++)
            shA[(tr * 4 + i) * 68 + tc * 4 + j] = fmaxf(acc[i][j] + bb[j], 0.f);
#pragma unroll
    for (int j = 0; j < 16; j++) {
        int idx = tid + j * 256;
        shW[(idx & 63) * 68 + (idx >> 6)] = W2[idx];
    }
    __syncthreads();

#pragma unroll
    for (int i = 0; i < 4; i++)
#pragma unroll
        for (int j = 0; j < 4; j++) acc[i][j] = 0.f;

    for (int k = 0; k < 64; k++) {
        float4 wv = *(const float4*)&shW[k * 68 + tc * 4];
        float a0 = shA[(tr * 4 + 0) * 68 + k];
        float a1 = shA[(tr * 4 + 1) * 68 + k];
        float a2 = shA[(tr * 4 + 2) * 68 + k];
        float a3 = shA[(tr * 4 + 3) * 68 + k];
        acc[0][0] += a0 * wv.x; acc[0][1] += a0 * wv.y; acc[0][2] += a0 * wv.z; acc[0][3] += a0 * wv.w;
        acc[1][0] += a1 * wv.x; acc[1][1] += a1 * wv.y; acc[1][2] += a1 * wv.z; acc[1][3] += a1 * wv.w;
        acc[2][0] += a2 * wv.x; acc[2][1] += a2 * wv.y; acc[2][2] += a2 * wv.z; acc[2][3] += a2 * wv.w;
        acc[3][0] += a3 * wv.x; acc[3][1] += a3 * wv.y; acc[3][2] += a3 * wv.z; acc[3][3] += a3 * wv.w;
    }

#pragma unroll
    for (int j = 0; j < 4; j++) bb[j] = b2[tc * 4 + j];
    float cs[4] = {0.f, 0.f, 0.f, 0.f};
    float cq[4] = {0.f, 0.f, 0.f, 0.f};
#pragma unroll
    for (int i = 0; i < 4; i++) {
        int n = base + tr * 4 + i;
        float v0 = fmaxf(acc[i][0] + bb[0], 0.f);
        float v1 = fmaxf(acc[i][1] + bb[1], 0.f);
        float v2 = fmaxf(acc[i][2] + bb[2], 0.f);
        float v3 = fmaxf(acc[i][3] + bb[3], 0.f);
        if (n < NN) {
            *(float4*)&g_h[(size_t)n * D + tc * 4] = make_float4(v0, v1, v2, v3);
            cs[0] += v0; cs[1] += v1; cs[2] += v2; cs[3] += v3;
            cq[0] += v0 * v0; cq[1] += v1 * v1; cq[2] += v2 * v2; cq[3] += v3 * v3;
        }
    }
#pragma unroll
    for (int j = 0; j < 4; j++) {
        atomicAdd(&red[tc * 4 + j], cs[j]);
        atomicAdd(&red[D + tc * 4 + j], cq[j]);
    }
    __syncthreads();
    if (tid < 2 * D) atomicAdd(&g_stats[tid], (double)red[tid]);
}

// ---------------------------------------------------------------------------
// finalize BN stats (and reset accumulators for next layer)
// ---------------------------------------------------------------------------
__global__ void finalize_kernel() {
    int f = threadIdx.x;
    double s = g_stats[f];
    double q = g_stats[D + f];
    double mu = s / (double)NN;
    double var = q / (double)NN - mu * mu;
    g_mu[f] = (float)mu;
    g_rs[f] = (float)(1.0 / sqrt(var + (double)BN_EPS));
    g_stats[f] = 0.0;
    g_stats[D + f] = 0.0;
}

// ---------------------------------------------------------------------------
// normalize + write xs + next-layer x (fp32 + fp16) + pooled segment-sum
// ---------------------------------------------------------------------------
__global__ void norm_kernel(const float* __restrict__ gamma,
                            const float* __restrict__ beta,
                            const int* __restrict__ batch,
                            float* __restrict__ out_pool,
                            float* __restrict__ out_xs, int layer) {
    int tid = threadIdx.x;
    int f = tid & 63;
    int sub = tid >> 6;   // 0..3
    int base = blockIdx.x * 128;
    float gm = gamma[f], bt = beta[f], mu = g_mu[f], rs = g_rs[f];
    __half* xh = (__half*)g_xh;
    int gcur = -1;
    float acc = 0.f;
    for (int j = 0; j < 32; j++) {
        int n = base + sub + j * 4;
        if (n >= NN) break;
        float h = g_h[(size_t)n * D + f];
        float y = gm * (h - mu) * rs + bt;
        if (out_xs)
            out_xs[(size_t)n * (NL * D) + layer * D + f] = y;
        g_x[(size_t)n * D + f] = y;
        xh[(size_t)n * D + f] = __float2half_rn(y);
        if (out_pool) {
            int g = batch[n];
            if (g != gcur) {
                if (gcur >= 0 && gcur < NG)
                    atomicAdd(&out_pool[(size_t)gcur * (NL * D) + layer * D + f], acc);
                gcur = g;
                acc = 0.f;
            }
            acc += y;
        }
    }
    if (out_pool && gcur >= 0 && gcur < NG)
        atomicAdd(&out_pool[(size_t)gcur * (NL * D) + layer * D + f], acc);
}

// ---------------------------------------------------------------------------
extern "C" void kernel_launch(void* const* d_in, const int* in_sizes, int n_in,
                              void* d_out, int out_size) {
    const float *x = 0, *ew = 0, *W1 = 0, *b1 = 0, *W2 = 0, *b2 = 0,
                *gamma = 0, *beta = 0;
    const int *ei = 0, *batch = 0;
    int n12288 = 0, n192 = 0;
    for (int i = 0; i < n_in; i++) {
        int s = in_sizes[i];
        const void* p = d_in[i];
        if (s == NN * D) x = (const float*)p;
        else if (s == 2 * NE) ei = (const int*)p;
        else if (s == NE) ew = (const float*)p;
        else if (s == NN) batch = (const int*)p;
        else if (s == NL * D * D) {
            if (n12288 == 0) W1 = (const float*)p; else W2 = (const float*)p;
            n12288++;
        } else if (s == NL * D) {
            if (n192 == 0) b1 = (const float*)p;
            else if (n192 == 1) b2 = (const float*)p;
            else if (n192 == 2) gamma = (const float*)p;
            else beta = (const float*)p;
            n192++;
        }
    }

    float* out = (float*)d_out;
    float* out_pool = 0;
    float* out_xs = 0;
    const int POOL_SZ = NG * NL * D;     // 98304
    const int XS_SZ = NN * NL * D;       // 19200000
    if (out_size >= POOL_SZ + XS_SZ) { out_pool = out; out_xs = out + POOL_SZ; }
    else if (out_size >= XS_SZ) { out_xs = out; }
    else { out_pool = out; }

    init_kernel<<<512, 256>>>(x, out_pool);

    // CSR build (once per call, amortized over 3 layers)
    deg_kernel<<<(NE + 255) / 256, 256>>>(ei);
    scanA_kernel<<<NSCAN, SCAN_BLK>>>();
    scanB_kernel<<<1, 128>>>();
    scanC_kernel<<<(NN + 255) / 256, 256>>>();
    fill_kernel<<<(NE + 255) / 256, 256>>>(ei, ew);

    int agg_blocks = (NN * 32 + 255) / 256;          // 12500
    int mlp_blocks = (NN + 63) / 64;                 // 1563
    int norm_blocks = (NN + 127) / 128;              // 782

    for (int i = 0; i < NL; i++) {
        int use_gx = (i > 0) ? 1 : 0;
        agg_kernel<<<agg_blocks, 256>>>(x, use_gx);
        mlp_kernel<<<mlp_blocks, 256>>>(W1 + i * D * D, b1 + i * D,
                                        W2 + i * D * D, b2 + i * D);
        finalize_kernel<<<1, D>>>();
        norm_kernel<<<norm_blocks, 256>>>(gamma + i * D, beta + i * D,
                                          batch, out_pool, out_xs, i);
    }
}

// round 14
// speedup vs baseline: 1.0831x; 1.0831x over previous
#include <cuda_runtime.h>
#include <cuda_fp16.h>
#include <math.h>

#define NN 100000
#define NE 1200000
#define D 64
#define NG 512
#define NL 3
#define BN_EPS 1e-5

#define SCAN_BLK 1024
#define NSCAN ((NN + SCAN_BLK - 1) / SCAN_BLK)   // 98

// Scratch (static device arrays; allocation is forbidden).
// Invariant: g_deg == 0 and g_stats == 0 at entry of every kernel_launch:
//  - zero-initialized at module load (first call)
//  - g_deg re-zeroed by the last norm_kernel, g_stats by deginit_kernel.
__device__ float g_agg[(size_t)NN * D];   // holds agg + x (fused)
__device__ float g_h[(size_t)NN * D];
__device__ float g_x[(size_t)NN * D];
__device__ double g_stats[NL][2 * D];
__device__ int g_deg[NN];
__device__ int g_rowptr[NN];
__device__ int g_cursor[NN];
__device__ int g_bsum[NSCAN];
__device__ int2 g_edge[NE];               // {src, __float_as_int(w)}

// ---------------------------------------------------------------------------
// deginit: degree histogram (g_deg pre-zeroed invariant) + zero pool + stats
// ---------------------------------------------------------------------------
__global__ void deginit_kernel(const int* __restrict__ ei,
                               float* __restrict__ out_pool) {
    int gid = blockIdx.x * blockDim.x + threadIdx.x;
    if (gid < NE) {
        int dst = ei[NE + gid];
        if ((unsigned)dst < NN) atomicAdd(&g_deg[dst], 1);
    }
    if (out_pool && gid < NG * (NL * D)) out_pool[gid] = 0.f;
    if (gid < NL * 2 * D) (&g_stats[0][0])[gid] = 0.0;
}

// ---------------------------------------------------------------------------
// scanA: per-1024-chunk exclusive scan of degrees + chunk totals
// ---------------------------------------------------------------------------
__global__ void __launch_bounds__(SCAN_BLK) scanA_kernel() {
    __shared__ int sh[SCAN_BLK];
    int t = threadIdx.x;
    int i = blockIdx.x * SCAN_BLK + t;
    int v = (i < NN) ? g_deg[i] : 0;
    sh[t] = v;
    __syncthreads();
    for (int off = 1; off < SCAN_BLK; off <<= 1) {
        int add = (t >= off) ? sh[t - off] : 0;
        __syncthreads();
        sh[t] += add;
        __syncthreads();
    }
    if (i < NN) g_rowptr[i] = sh[t] - v;          // exclusive within chunk
    if (t == SCAN_BLK - 1) g_bsum[blockIdx.x] = sh[t];
}

// ---------------------------------------------------------------------------
// scanC: finalize rowptr/cursor; each block redundantly prefix-sums the 98
// chunk totals in smem (replaces the separate scanB launch).
// 256 threads; pre[] sized to blockDim (entries >= NSCAN are zero).
// ---------------------------------------------------------------------------
__global__ void __launch_bounds__(256) scanC_kernel() {
    __shared__ int pre[256];
    int t = threadIdx.x;
    int v = (t < NSCAN) ? g_bsum[t] : 0;
    pre[t] = v;
    __syncthreads();
    for (int off = 1; off < 256; off <<= 1) {
        int add = (t >= off) ? pre[t - off] : 0;
        __syncthreads();
        pre[t] += add;
        __syncthreads();
    }
    pre[t] -= v;                                  // inclusive -> exclusive
    __syncthreads();
    int i = blockIdx.x * blockDim.x + t;
    if (i < NN) {
        int r = g_rowptr[i] + pre[i / SCAN_BLK];
        g_rowptr[i] = r;
        g_cursor[i] = r;
    }
}

// ---------------------------------------------------------------------------
// fill: scatter edges into CSR slots
// ---------------------------------------------------------------------------
__global__ void fill_kernel(const int* __restrict__ ei,
                            const float* __restrict__ ew) {
    int e = blockIdx.x * blockDim.x + threadIdx.x;
    if (e < NE) {
        int src = ei[e];
        int dst = ei[NE + e];
        if ((unsigned)dst >= NN) return;
        int pos = atomicAdd(&g_cursor[dst], 1);
        g_edge[pos] = make_int2(src, __float_as_int(ew[e]));
    }
}

// ---------------------------------------------------------------------------
// gather-aggregate: warp per node. agg[n] = x[n] + sum_e w_e * x[src_e]
// ---------------------------------------------------------------------------
__global__ void __launch_bounds__(256) agg_kernel(const float* __restrict__ x_in,
                                                  int use_gx) {
    const float* __restrict__ x = use_gx ? g_x : x_in;
    int wid = (blockIdx.x * blockDim.x + threadIdx.x) >> 5;
    int lane = threadIdx.x & 31;
    if (wid >= NN) return;
    int start = g_rowptr[wid];
    int deg = g_deg[wid];
    float a0 = 0.f, a1 = 0.f;
    int e = 0;
    for (; e + 2 <= deg; e += 2) {
        int2 e0 = g_edge[start + e];
        int2 e1 = g_edge[start + e + 1];
        float w0 = __int_as_float(e0.y);
        float w1 = __int_as_float(e1.y);
        const float* r0 = x + (size_t)e0.x * D;
        const float* r1 = x + (size_t)e1.x * D;
        a0 += w0 * r0[lane];
        a1 += w0 * r0[lane + 32];
        a0 += w1 * r1[lane];
        a1 += w1 * r1[lane + 32];
    }
    if (e < deg) {
        int2 e0 = g_edge[start + e];
        float w0 = __int_as_float(e0.y);
        const float* r0 = x + (size_t)e0.x * D;
        a0 += w0 * r0[lane];
        a1 += w0 * r0[lane + 32];
    }
    const float* xn = x + (size_t)wid * D;
    g_agg[(size_t)wid * D + lane] = a0 + xn[lane];
    g_agg[(size_t)wid * D + lane + 32] = a1 + xn[lane + 32];
}

// ---------------------------------------------------------------------------
// fused MLP: h = relu(relu(A@W1^T + b1)@W2^T + b2), + BN partial sums
// A = g_agg (already includes +x). 64-row tile, 256 threads, 4x4 blocking.
// ---------------------------------------------------------------------------
__global__ void __launch_bounds__(256) mlp_kernel(
    const float* __restrict__ W1, const float* __restrict__ b1,
    const float* __restrict__ W2, const float* __restrict__ b2,
    int layer) {
    __shared__ __align__(16) float shA[64 * 68];
    __shared__ __align__(16) float shW[64 * 68];
    __shared__ float red[2 * D];

    int tid = threadIdx.x;
    int base = blockIdx.x * 64;
    if (tid < 2 * D) red[tid] = 0.f;

#pragma unroll
    for (int j = 0; j < 16; j++) {
        int idx = tid + j * 256;
        int r = idx >> 6, k = idx & 63;
        int n = base + r;
        shA[r * 68 + k] = (n < NN) ? g_agg[(size_t)n * D + k] : 0.f;
    }
#pragma unroll
    for (int j = 0; j < 16; j++) {
        int idx = tid + j * 256;
        shW[(idx & 63) * 68 + (idx >> 6)] = W1[idx];
    }
    __syncthreads();

    int tr = tid >> 4, tc = tid & 15;
    float acc[4][4];
#pragma unroll
    for (int i = 0; i < 4; i++)
#pragma unroll
        for (int j = 0; j < 4; j++) acc[i][j] = 0.f;

    for (int k = 0; k < 64; k++) {
        float4 wv = *(const float4*)&shW[k * 68 + tc * 4];
        float a0 = shA[(tr * 4 + 0) * 68 + k];
        float a1 = shA[(tr * 4 + 1) * 68 + k];
        float a2 = shA[(tr * 4 + 2) * 68 + k];
        float a3 = shA[(tr * 4 + 3) * 68 + k];
        acc[0][0] += a0 * wv.x; acc[0][1] += a0 * wv.y; acc[0][2] += a0 * wv.z; acc[0][3] += a0 * wv.w;
        acc[1][0] += a1 * wv.x; acc[1][1] += a1 * wv.y; acc[1][2] += a1 * wv.z; acc[1][3] += a1 * wv.w;
        acc[2][0] += a2 * wv.x; acc[2][1] += a2 * wv.y; acc[2][2] += a2 * wv.z; acc[2][3] += a2 * wv.w;
        acc[3][0] += a3 * wv.x; acc[3][1] += a3 * wv.y; acc[3][2] += a3 * wv.z; acc[3][3] += a3 * wv.w;
    }
    __syncthreads();

    float bb[4];
#pragma unroll
    for (int j = 0; j < 4; j++) bb[j] = b1[tc * 4 + j];
#pragma unroll
    for (int i = 0; i < 4; i++)
#pragma unroll
        for (int j = 0; j < 4; j++)
            shA[(tr * 4 + i) * 68 + tc * 4 + j] = fmaxf(acc[i][j] + bb[j], 0.f);
#pragma unroll
    for (int j = 0; j < 16; j++) {
        int idx = tid + j * 256;
        shW[(idx & 63) * 68 + (idx >> 6)] = W2[idx];
    }
    __syncthreads();

#pragma unroll
    for (int i = 0; i < 4; i++)
#pragma unroll
        for (int j = 0; j < 4; j++) acc[i][j] = 0.f;

    for (int k = 0; k < 64; k++) {
        float4 wv = *(const float4*)&shW[k * 68 + tc * 4];
        float a0 = shA[(tr * 4 + 0) * 68 + k];
        float a1 = shA[(tr * 4 + 1) * 68 + k];
        float a2 = shA[(tr * 4 + 2) * 68 + k];
        float a3 = shA[(tr * 4 + 3) * 68 + k];
        acc[0][0] += a0 * wv.x; acc[0][1] += a0 * wv.y; acc[0][2] += a0 * wv.z; acc[0][3] += a0 * wv.w;
        acc[1][0] += a1 * wv.x; acc[1][1] += a1 * wv.y; acc[1][2] += a1 * wv.z; acc[1][3] += a1 * wv.w;
        acc[2][0] += a2 * wv.x; acc[2][1] += a2 * wv.y; acc[2][2] += a2 * wv.z; acc[2][3] += a2 * wv.w;
        acc[3][0] += a3 * wv.x; acc[3][1] += a3 * wv.y; acc[3][2] += a3 * wv.z; acc[3][3] += a3 * wv.w;
    }

#pragma unroll
    for (int j = 0; j < 4; j++) bb[j] = b2[tc * 4 + j];
    float cs[4] = {0.f, 0.f, 0.f, 0.f};
    float cq[4] = {0.f, 0.f, 0.f, 0.f};
#pragma unroll
    for (int i = 0; i < 4; i++) {
        int n = base + tr * 4 + i;
        float v0 = fmaxf(acc[i][0] + bb[0], 0.f);
        float v1 = fmaxf(acc[i][1] + bb[1], 0.f);
        float v2 = fmaxf(acc[i][2] + bb[2], 0.f);
        float v3 = fmaxf(acc[i][3] + bb[3], 0.f);
        if (n < NN) {
            *(float4*)&g_h[(size_t)n * D + tc * 4] = make_float4(v0, v1, v2, v3);
            cs[0] += v0; cs[1] += v1; cs[2] += v2; cs[3] += v3;
            cq[0] += v0 * v0; cq[1] += v1 * v1; cq[2] += v2 * v2; cq[3] += v3 * v3;
        }
    }
#pragma unroll
    for (int j = 0; j < 4; j++) {
        atomicAdd(&red[tc * 4 + j], cs[j]);
        atomicAdd(&red[D + tc * 4 + j], cq[j]);
    }
    __syncthreads();
    if (tid < 2 * D) atomicAdd(&g_stats[layer][tid], (double)red[tid]);
}

// ---------------------------------------------------------------------------
// normalize + write xs + next-layer x + pooled segment-sum (batch sorted).
// mu/rs computed inline from per-layer stats slot (no finalize launch).
// Last layer also re-zeroes g_deg to restore the cross-call invariant.
// ---------------------------------------------------------------------------
__global__ void norm_kernel(const float* __restrict__ gamma,
                            const float* __restrict__ beta,
                            const int* __restrict__ batch,
                            float* __restrict__ out_pool,
                            float* __restrict__ out_xs, int layer) {
    int tid = threadIdx.x;
    int f = tid & 63;
    int sub = tid >> 6;   // 0..3
    int base = blockIdx.x * 128;

    if (layer == NL - 1) {
        int gidx = blockIdx.x * blockDim.x + tid;   // 782*256 > NN, covers all
        if (gidx < NN) g_deg[gidx] = 0;
    }

    const double inv_n = 1.0 / (double)NN;
    double mud = g_stats[layer][f] * inv_n;
    double qd = g_stats[layer][D + f] * inv_n;
    float mu = (float)mud;
    float var = (float)(qd - mud * mud);
    float rs = rsqrtf(var + (float)BN_EPS);
    float gm = gamma[f], bt = beta[f];

    int gcur = -1;
    float acc = 0.f;
    for (int j = 0; j < 32; j++) {
        int n = base + sub + j * 4;
        if (n >= NN) break;
        float h = g_h[(size_t)n * D + f];
        float y = gm * (h - mu) * rs + bt;
        if (out_xs)
            out_xs[(size_t)n * (NL * D) + layer * D + f] = y;
        g_x[(size_t)n * D + f] = y;
        if (out_pool) {
            int g = batch[n];
            if (g != gcur) {
                if (gcur >= 0 && gcur < NG)
                    atomicAdd(&out_pool[(size_t)gcur * (NL * D) + layer * D + f], acc);
                gcur = g;
                acc = 0.f;
            }
            acc += y;
        }
    }
    if (out_pool && gcur >= 0 && gcur < NG)
        atomicAdd(&out_pool[(size_t)gcur * (NL * D) + layer * D + f], acc);
}

// ---------------------------------------------------------------------------
extern "C" void kernel_launch(void* const* d_in, const int* in_sizes, int n_in,
                              void* d_out, int out_size) {
    const float *x = 0, *ew = 0, *W1 = 0, *b1 = 0, *W2 = 0, *b2 = 0,
                *gamma = 0, *beta = 0;
    const int *ei = 0, *batch = 0;
    int n12288 = 0, n192 = 0;
    for (int i = 0; i < n_in; i++) {
        int s = in_sizes[i];
        const void* p = d_in[i];
        if (s == NN * D) x = (const float*)p;
        else if (s == 2 * NE) ei = (const int*)p;
        else if (s == NE) ew = (const float*)p;
        else if (s == NN) batch = (const int*)p;
        else if (s == NL * D * D) {
            if (n12288 == 0) W1 = (const float*)p; else W2 = (const float*)p;
            n12288++;
        } else if (s == NL * D) {
            if (n192 == 0) b1 = (const float*)p;
            else if (n192 == 1) b2 = (const float*)p;
            else if (n192 == 2) gamma = (const float*)p;
            else beta = (const float*)p;
            n192++;
        }
    }

    float* out = (float*)d_out;
    float* out_pool = 0;
    float* out_xs = 0;
    const int POOL_SZ = NG * NL * D;     // 98304
    const int XS_SZ = NN * NL * D;       // 19200000
    if (out_size >= POOL_SZ + XS_SZ) { out_pool = out; out_xs = out + POOL_SZ; }
    else if (out_size >= XS_SZ) { out_xs = out; }
    else { out_pool = out; }

    // CSR build + init (g_deg/g_stats zero-at-entry invariant)
    deginit_kernel<<<(NE + 255) / 256, 256>>>(ei, out_pool);
    scanA_kernel<<<NSCAN, SCAN_BLK>>>();
    scanC_kernel<<<(NN + 255) / 256, 256>>>();
    fill_kernel<<<(NE + 255) / 256, 256>>>(ei, ew);

    int agg_blocks = (NN * 32 + 255) / 256;          // 12500
    int mlp_blocks = (NN + 63) / 64;                 // 1563
    int norm_blocks = (NN + 127) / 128;              // 782

    for (int i = 0; i < NL; i++) {
        int use_gx = (i > 0) ? 1 : 0;
        agg_kernel<<<agg_blocks, 256>>>(x, use_gx);
        mlp_kernel<<<mlp_blocks, 256>>>(W1 + i * D * D, b1 + i * D,
                                        W2 + i * D * D, b2 + i * D, i);
        norm_kernel<<<norm_blocks, 256>>>(gamma + i * D, beta + i * D,
                                          batch, out_pool, out_xs, i);
    }
}